// round 16
// baseline (speedup 1.0000x reference)
#include <cuda_runtime.h>
#include <cstdint>

#define B_SZ 512
#define IN_F 512
#define OUT_F 100
#define KD 5
#define OC 500              // OUT_F * KD
#define LOG2E 1.4426950408889634f
#define NT 32               // number of batch tiles
#define TS 16               // tile size (NT*TS = B_SZ)
#define NP 528              // NT*(NT+1)/2 unordered tile pairs

// Scratch for M = (x @ T) * log2(e), laid out [b][o*5+k], 512x500 floats = 1MB
__device__ float g_M[B_SZ * OC];

__device__ __forceinline__ float ex2(float x) {
    float r;
    asm("ex2.approx.f32 %0, %1;" : "=f"(r) : "f"(x));
    return r;
}

// ---------------------------------------------------------------------------
// Kernel 1 (EXACT R6/R15 gemm — best measured): M[b][oc] =
// sum_i x[b][i] * T[i][oc], scaled by log2e. Block: 512 threads = 64
// oc-pair-lanes x 8 K-slices (kh); 8 b-rows x 2 oc per thread (float2 T
// loads) over a 64-long K-slice; slices reduced through 28KB smem (linear).
// Grid (64, 4). Also zeroes `out` (blockIdx.y == 0 slice).
// ---------------------------------------------------------------------------
__global__ void __launch_bounds__(512) gemm_kernel(const float* __restrict__ x,
                                                   const float* __restrict__ T,
                                                   float* __restrict__ out) {
    __shared__ __align__(16) float xs[IN_F * 8];          // [i][bb], 16KB
    __shared__ __align__(16) float red[7 * 8 * 128];      // kh=1..7 partials, 28KB

    const int t = threadIdx.x;
    const int lane = t & 63;               // oc-pair lane
    const int kh = t >> 6;                 // 0..7
    const int b0 = blockIdx.x * 8;
    const int oc0 = blockIdx.y * 128;
    const int oc = oc0 + lane * 2;
    const bool ocv = (oc < OC);

    if (blockIdx.y == 0) {
        for (int idx = blockIdx.x * 512 + t; idx < B_SZ * OUT_F; idx += 64 * 512)
            out[idx] = 0.0f;
    }

    // cooperative transpose load: x[b0+bb][i] -> xs[i*8+bb]
    for (int idx = t; idx < IN_F * 8; idx += 512) {
        int bb = idx >> 9;
        int i = idx & (IN_F - 1);
        xs[i * 8 + bb] = x[(b0 + bb) * IN_F + i];
    }
    __syncthreads();

    float accx[8] = {0.f, 0.f, 0.f, 0.f, 0.f, 0.f, 0.f, 0.f};
    float accy[8] = {0.f, 0.f, 0.f, 0.f, 0.f, 0.f, 0.f, 0.f};

    if (ocv) {
        const float* tp = T + (size_t)(kh * 64) * OC + oc;
        const float* xp = xs + kh * 64 * 8;
#pragma unroll 8
        for (int i = 0; i < 64; i++) {
            float2 tv = *reinterpret_cast<const float2*>(tp + i * OC);
            float4 xa = *reinterpret_cast<const float4*>(xp + i * 8);
            float4 xb = *reinterpret_cast<const float4*>(xp + i * 8 + 4);
            accx[0] += xa.x * tv.x; accy[0] += xa.x * tv.y;
            accx[1] += xa.y * tv.x; accy[1] += xa.y * tv.y;
            accx[2] += xa.z * tv.x; accy[2] += xa.z * tv.y;
            accx[3] += xa.w * tv.x; accy[3] += xa.w * tv.y;
            accx[4] += xb.x * tv.x; accy[4] += xb.x * tv.y;
            accx[5] += xb.y * tv.x; accy[5] += xb.y * tv.y;
            accx[6] += xb.z * tv.x; accy[6] += xb.z * tv.y;
            accx[7] += xb.w * tv.x; accy[7] += xb.w * tv.y;
        }
    }

    if (kh > 0) {
        float* rp = red + (kh - 1) * 1024 + lane * 2;
#pragma unroll
        for (int bb = 0; bb < 8; bb++) {
            rp[bb * 128 + 0] = accx[bb];
            rp[bb * 128 + 1] = accy[bb];
        }
    }
    __syncthreads();
    if (kh == 0 && ocv) {
#pragma unroll
        for (int bb = 0; bb < 8; bb++) {
            float sx = accx[bb], sy = accy[bb];
#pragma unroll
            for (int s = 0; s < 7; s++) {
                sx += red[s * 1024 + bb * 128 + lane * 2 + 0];
                sy += red[s * 1024 + bb * 128 + lane * 2 + 1];
            }
            float2 o2;
            o2.x = sx * LOG2E;
            o2.y = sy * LOG2E;
            *reinterpret_cast<float2*>(&g_M[(size_t)(b0 + bb) * OC + oc]) = o2;
        }
    }
}

// ---------------------------------------------------------------------------
// Kernel 2 (EXACT R15 md + PDL grid-dependency sync): symmetric, branchless
// hot loop on the unpadded stride-5 layout. One block per unordered tile
// pair, 528 blocks, 416 threads; t<400: o = t>>2, jl = t&3, JR=4 named-
// scalar j-rows. Launched with programmatic stream serialization: blocks are
// scheduled during gemm's drain and run the prologue (pair decode, index
// math, accI init) before cudaGridDependencySynchronize() gates the first
// g_M / out access.
// ---------------------------------------------------------------------------
__global__ void __launch_bounds__(416, 2) md_kernel(float* __restrict__ out) {
    __shared__ __align__(16) float ms[TS * OC];  // 32KB

    int rem = blockIdx.x;
    int ta = 0;
    while (rem >= NT - ta) { rem -= NT - ta; ta++; }
    const int tb = ta + rem;
    const bool diag = (ta == tb);

    const int t = threadIdx.x;
    const bool act = (t < 400);
    const int o = act ? (t >> 2) : 99;   // clamp for safe reads
    const int jl = t & 3;

    float accI[TS];   // compile-time indexed only -> registers
#pragma unroll
    for (int ii = 0; ii < TS; ii++) accI[ii] = 0.f;

    // Wait for gemm's g_M / out writes to be visible (PDL dependency gate).
    cudaGridDependencySynchronize();

    // stage tile_a: 16 rows x 500 floats = 2000 float4
    {
        const float4* src = reinterpret_cast<const float4*>(g_M + (size_t)ta * TS * OC);
        float4* dst = reinterpret_cast<float4*>(ms);
        for (int i = t; i < 2000; i += 416) dst[i] = src[i];
    }

    // load 4 j-side rows into NAMED scalars
#define DECL_A(R)                                                              \
    float a##R##0, a##R##1, a##R##2, a##R##3, a##R##4;                         \
    {                                                                          \
        const int j = tb * TS + jl + 4 * (R);                                  \
        const float* m = g_M + (size_t)j * OC + o * KD;                        \
        a##R##0 = m[0]; a##R##1 = m[1]; a##R##2 = m[2];                        \
        a##R##3 = m[3]; a##R##4 = m[4];                                        \
    }
    DECL_A(0)
    DECL_A(1)
    DECL_A(2)
    DECL_A(3)
#undef DECL_A

    float accJ0 = 0.f, accJ1 = 0.f, accJ2 = 0.f, accJ3 = 0.f;

    __syncthreads();

    const float* mp = ms + o * KD;

#define EVAL(R, ACC)                                                           \
    {                                                                          \
        float pa = -fabsf(d0 - a##R##0) - fabsf(d1 - a##R##1);                 \
        float qa = -fabsf(d2 - a##R##2) - fabsf(d3 - a##R##3);                 \
        float n = (pa + qa) - fabsf(d4 - a##R##4);                             \
        float e = ex2(n);                                                      \
        ACC += e;                                                              \
        loc += e;                                                              \
    }

#pragma unroll
    for (int ii = 0; ii < TS; ii++) {
        const float* m = mp + ii * OC;
        float d0 = m[0], d1 = m[1], d2 = m[2], d3 = m[3], d4 = m[4];
        float loc = 0.f;
        EVAL(0, accJ0)
        EVAL(1, accJ1)
        EVAL(2, accJ2)
        EVAL(3, accJ3)
        accI[ii] = loc;
    }
#undef EVAL

    // Epilogue: butterfly-reduce each accI[ii] across the 4 jl-lanes.
#pragma unroll
    for (int ii = 0; ii < TS; ii++) {
        float v = accI[ii];
        v += __shfl_xor_sync(0xffffffffu, v, 1);
        v += __shfl_xor_sync(0xffffffffu, v, 2);
        accI[ii] = v;
    }

    if (act) {
        if (!diag) {
            // lane jl writes rows ii = jl*4 + q; compile-time selection only
#pragma unroll
            for (int q = 0; q < 4; q++) {
                float v = (jl == 0) ? accI[q]
                        : (jl == 1) ? accI[4 + q]
                        : (jl == 2) ? accI[8 + q]
                                    : accI[12 + q];
                const int ii = jl * 4 + q;
                atomicAdd(&out[(ta * TS + ii) * OUT_F + o], v);
            }
        }
        const float sub = diag ? 1.0f : 0.0f;
        atomicAdd(&out[(tb * TS + jl + 0)  * OUT_F + o], accJ0 - sub);
        atomicAdd(&out[(tb * TS + jl + 4)  * OUT_F + o], accJ1 - sub);
        atomicAdd(&out[(tb * TS + jl + 8)  * OUT_F + o], accJ2 - sub);
        atomicAdd(&out[(tb * TS + jl + 12) * OUT_F + o], accJ3 - sub);
    }
}

extern "C" void kernel_launch(void* const* d_in, const int* in_sizes, int n_in,
                              void* d_out, int out_size) {
    const float* x = (const float*)d_in[0];   // [512, 512]
    const float* T = (const float*)d_in[1];   // [512, 100, 5] -> [512, 500]
    float* out = (float*)d_out;               // [512, 100]

    gemm_kernel<<<dim3(64, 4), 512>>>(x, T, out);

    // md with programmatic dependent launch: overlap its scheduling/prologue
    // with gemm's drain; cudaGridDependencySynchronize() in-kernel gates the
    // first dependent memory access.
    cudaLaunchConfig_t cfg = {};
    cfg.gridDim = dim3(NP, 1, 1);
    cfg.blockDim = dim3(416, 1, 1);
    cudaLaunchAttribute attrs[1];
    attrs[0].id = cudaLaunchAttributeProgrammaticStreamSerialization;
    attrs[0].val.programmaticStreamSerializationAllowed = 1;
    cfg.attrs = attrs;
    cfg.numAttrs = 1;
    cudaError_t err = cudaLaunchKernelEx(&cfg, md_kernel, out);
    if (err != cudaSuccess) {
        // PDL unavailable -> plain launch (correctness preserved)
        md_kernel<<<NP, 416>>>(out);
    }
}